// round 4
// baseline (speedup 1.0000x reference)
#include <cuda_runtime.h>
#include <cuda_bf16.h>
#include <math.h>

// Problem constants
#define BB    4
#define TT    4096
#define DIM   1024
#define HEADS 16
#define DH    64
#define MTOT  (BB*TT)     // 16384
#define QKVN  3072
#define SCALEF 0.125f     // 64^-0.5
#define NPART 4           // T-split for context kernel

// ---------------- scratch (device globals: allocation-free) ----------------
__device__ float g_qkv[(size_t)MTOT * QKVN];          // 192 MiB: [m][3072] (q|k|v)
__device__ float g_keep[MTOT];                        // 1.0 = keep, 0.0 = padded
__device__ float g_pm[BB * DIM * 8];                  // partial max  per (b,col,chunk)
__device__ float g_ps[BB * DIM * 8];                  // partial sumexp
__device__ float g_cmax[BB * DIM];
__device__ float g_crcp[BB * DIM];                    // 1/sum
__device__ float g_ctxp[NPART][(size_t)BB * HEADS * DH * DH]; // context partials
__device__ float g_Mb[(size_t)BB * DIM * DIM];        // 16 MiB fused (SCALE*ctx@Wout)
__device__ int   g_flags[3];

// ---------------- mask dtype detection + conversion ----------------
__global__ void init_flags_kernel() {
    if (threadIdx.x < 3) g_flags[threadIdx.x] = 0;
}

// Scan the first 16384 bytes (always in-bounds for u8/i32/f32/bf16 buffers).
// flag0: any byte > 1           -> float-ish (f32 or bf16)
// flag1: byte==1 at idx%4 != 0  -> u8
// flag2: byte==0x3F at idx%4==1 -> bf16 (f32 0/1 only puts 0x3F at idx%4==3)
__global__ void detect_mask_kernel(const unsigned char* __restrict__ p) {
    int i = blockIdx.x * blockDim.x + threadIdx.x;
    if (i >= MTOT) return;
    unsigned char v = p[i];
    if (v > 1) atomicOr(&g_flags[0], 1);
    if (v == 1 && (i & 3)) atomicOr(&g_flags[1], 1);
    if (v == 0x3F && (i & 3) == 1) atomicOr(&g_flags[2], 1);
}

__global__ void convert_mask_kernel(const void* __restrict__ p) {
    int i = blockIdx.x * blockDim.x + threadIdx.x;
    if (i >= MTOT) return;
    int f0 = g_flags[0], f1 = g_flags[1], f2 = g_flags[2];
    bool masked;
    if (f2) {                 // bf16
        masked = (__bfloat162float(((const __nv_bfloat16*)p)[i]) != 0.0f);
    } else if (f0) {          // float32
        masked = (((const float*)p)[i] != 0.0f);
    } else if (f1) {          // uint8 / int8 bool
        masked = (((const unsigned char*)p)[i] != 0);
    } else {                  // int32
        masked = (((const int*)p)[i] != 0);
    }
    g_keep[i] = masked ? 0.0f : 1.0f;
}

// ---------------- generic fp32 SGEMM: C = A@B (+bias), 128x128x8, 8x8/thread ----------------
__global__ __launch_bounds__(256)
void sgemm_kernel(const float* __restrict__ A, const float* __restrict__ Bm,
                  float* __restrict__ C, const float* __restrict__ bias,
                  int K, int lda, int ldb, int ldc,
                  long long aBS, long long bBS, long long cBS)
{
    __shared__ float As[8][128];
    __shared__ float Bs[8][128];

    A  += (long long)blockIdx.z * aBS;
    Bm += (long long)blockIdx.z * bBS;
    C  += (long long)blockIdx.z * cBS;

    const int tid  = threadIdx.x;
    const int row0 = blockIdx.y * 128;
    const int col0 = blockIdx.x * 128;

    const int aRow = tid >> 1;           // 0..127
    const int aCol = (tid & 1) * 4;      // 0 or 4
    const int bRow = tid >> 5;           // 0..7
    const int bCol = (tid & 31) * 4;     // 0..124

    const float* Ap = A  + (long long)(row0 + aRow) * lda + aCol;
    const float* Bp = Bm + (long long)bRow * ldb + col0 + bCol;

    float acc[8][8];
#pragma unroll
    for (int i = 0; i < 8; i++)
#pragma unroll
        for (int j = 0; j < 8; j++) acc[i][j] = 0.0f;

    const int ty = tid >> 4;   // 0..15  -> rows ty*8..ty*8+7
    const int tx = tid & 15;   // 0..15  -> cols tx*8..tx*8+7

    for (int k0 = 0; k0 < K; k0 += 8) {
        float4 av = *(const float4*)Ap;
        float4 bv = *(const float4*)Bp;
        __syncthreads();   // previous tile fully consumed
        As[aCol + 0][aRow] = av.x;
        As[aCol + 1][aRow] = av.y;
        As[aCol + 2][aRow] = av.z;
        As[aCol + 3][aRow] = av.w;
        *(float4*)&Bs[bRow][bCol] = bv;
        __syncthreads();

#pragma unroll
        for (int kk = 0; kk < 8; kk++) {
            float a[8], b[8];
            *(float4*)&a[0] = *(const float4*)&As[kk][ty * 8];
            *(float4*)&a[4] = *(const float4*)&As[kk][ty * 8 + 4];
            *(float4*)&b[0] = *(const float4*)&Bs[kk][tx * 8];
            *(float4*)&b[4] = *(const float4*)&Bs[kk][tx * 8 + 4];
#pragma unroll
            for (int i = 0; i < 8; i++)
#pragma unroll
                for (int j = 0; j < 8; j++) acc[i][j] = fmaf(a[i], b[j], acc[i][j]);
        }
        Ap += 8;
        Bp += (long long)8 * ldb;
    }

#pragma unroll
    for (int i = 0; i < 8; i++) {
        long long r = row0 + ty * 8 + i;
#pragma unroll
        for (int j4 = 0; j4 < 8; j4 += 4) {
            int c = col0 + tx * 8 + j4;
            float4 v;
            v.x = acc[i][j4 + 0]; v.y = acc[i][j4 + 1];
            v.z = acc[i][j4 + 2]; v.w = acc[i][j4 + 3];
            if (bias) {
                v.x += bias[c + 0]; v.y += bias[c + 1];
                v.z += bias[c + 2]; v.w += bias[c + 3];
            }
            *(float4*)&C[r * ldc + c] = v;
        }
    }
}

// ---------------- column softmax stats over T (online max/sum) ----------------
#define TCH 512
__global__ void colstats_partial_kernel() {
    int col = blockIdx.x * 256 + threadIdx.x;   // 0..1023
    int ch  = blockIdx.y;                       // 0..7
    int b   = blockIdx.z;                       // 0..3
    const float* p = g_qkv + (size_t)(b * TT + ch * TCH) * QKVN + DIM + col;
    float m = -1e30f, s = 0.0f;
#pragma unroll 4
    for (int t = 0; t < TCH; t++) {
        float v = *p; p += QKVN;
        if (v > m) { s *= __expf(m - v); m = v; }
        s += __expf(v - m);
    }
    g_pm[(b * DIM + col) * 8 + ch] = m;
    g_ps[(b * DIM + col) * 8 + ch] = s;
}

__global__ void colstats_combine_kernel() {
    int i = blockIdx.x * 256 + threadIdx.x;     // 0..4095
    float m = -1e30f;
#pragma unroll
    for (int c = 0; c < 8; c++) m = fmaxf(m, g_pm[i * 8 + c]);
    float s = 0.0f;
#pragma unroll
    for (int c = 0; c < 8; c++) s += g_ps[i * 8 + c] * __expf(g_pm[i * 8 + c] - m);
    g_cmax[i] = m;
    g_crcp[i] = 1.0f / s;
}

// ---------------- context partial: ctx[p][b,h,d,e] = sum_{t in part} softk(t,d)*v(t,e) ----------------
__global__ __launch_bounds__(256)
void context_part_kernel() {
    int h = blockIdx.x, b = blockIdx.y, part = blockIdx.z;
    __shared__ float wk[32][64];
    __shared__ float vv[32][64];
    __shared__ float smax[64], srcp[64];

    int tid = threadIdx.x;
    if (tid < 64) {
        smax[tid] = g_cmax[b * DIM + h * DH + tid];
        srcp[tid] = g_crcp[b * DIM + h * DH + tid];
    }
    __syncthreads();

    int tx = tid & 15, ty = tid >> 4;   // d0 = tx*4, e0 = ty*4
    float acc[4][4];
#pragma unroll
    for (int i = 0; i < 4; i++)
#pragma unroll
        for (int j = 0; j < 4; j++) acc[i][j] = 0.0f;

    int t0base = part * (TT / NPART);
    for (int t0 = t0base; t0 < t0base + TT / NPART; t0 += 32) {
#pragma unroll
        for (int l = 0; l < 8; l++) {
            int idx = tid + l * 256;      // 0..2047
            int r = idx >> 6, c = idx & 63;
            int t = t0 + r;
            size_t base = (size_t)(b * TT + t) * QKVN + h * DH + c;
            float kv = g_qkv[base + DIM];
            float vl = g_qkv[base + 2 * DIM];
            wk[r][c] = g_keep[b * TT + t] * __expf(kv - smax[c]) * srcp[c];
            vv[r][c] = vl;
        }
        __syncthreads();
#pragma unroll
        for (int tt = 0; tt < 32; tt++) {
            float a[4], bb[4];
            *(float4*)a  = *(const float4*)&wk[tt][tx * 4];
            *(float4*)bb = *(const float4*)&vv[tt][ty * 4];
#pragma unroll
            for (int i = 0; i < 4; i++)
#pragma unroll
                for (int j = 0; j < 4; j++) acc[i][j] = fmaf(a[i], bb[j], acc[i][j]);
        }
        __syncthreads();
    }

    float* out = g_ctxp[part] + ((size_t)(b * HEADS + h) * DH) * DH;
#pragma unroll
    for (int i = 0; i < 4; i++) {
        float4 v;
        v.x = acc[i][0]; v.y = acc[i][1]; v.z = acc[i][2]; v.w = acc[i][3];
        *(float4*)&out[(tx * 4 + i) * DH + ty * 4] = v;
    }
}

// ---------------- Mb[b][h*64+d][n] = SCALE * sum_e ctx[b,h,d,e] * Wout[h*64+e][n] ----------------
__global__ __launch_bounds__(256)
void mb_kernel(const float* __restrict__ Wout) {
    int nt = blockIdx.x;                // 0..15 -> n0 = nt*64
    int h  = blockIdx.y & 15;
    int b  = blockIdx.y >> 4;
    __shared__ float cs[64][64];
    __shared__ float ws[16][64];

    int tid = threadIdx.x;
    size_t coff = ((size_t)(b * HEADS + h) * DH) * DH;
#pragma unroll
    for (int l = 0; l < 16; l++) {
        int idx = tid + l * 256;        // 0..4095
        float s = 0.0f;
#pragma unroll
        for (int p = 0; p < NPART; p++) s += g_ctxp[p][coff + idx];
        cs[idx >> 6][idx & 63] = s;
    }
    __syncthreads();

    int tx = tid & 15, ty = tid >> 4;   // d0 = ty*4, n-local = tx*4
    int n0 = nt * 64;
    float acc[4][4];
#pragma unroll
    for (int i = 0; i < 4; i++)
#pragma unroll
        for (int j = 0; j < 4; j++) acc[i][j] = 0.0f;

    for (int e0 = 0; e0 < 64; e0 += 16) {
#pragma unroll
        for (int l = 0; l < 4; l++) {
            int idx = tid + l * 256;    // 0..1023
            int ee = idx >> 6, nn = idx & 63;
            ws[ee][nn] = Wout[(size_t)(h * DH + e0 + ee) * DIM + n0 + nn];
        }
        __syncthreads();
#pragma unroll
        for (int ee = 0; ee < 16; ee++) {
            float a[4], bb[4];
#pragma unroll
            for (int i = 0; i < 4; i++) a[i] = cs[ty * 4 + i][e0 + ee];
            *(float4*)bb = *(const float4*)&ws[ee][tx * 4];
#pragma unroll
            for (int i = 0; i < 4; i++)
#pragma unroll
                for (int j = 0; j < 4; j++) acc[i][j] = fmaf(a[i], bb[j], acc[i][j]);
        }
        __syncthreads();
    }

    float* out = g_Mb + (size_t)b * DIM * DIM;
#pragma unroll
    for (int i = 0; i < 4; i++) {
        float4 v;
        v.x = acc[i][0] * SCALEF; v.y = acc[i][1] * SCALEF;
        v.z = acc[i][2] * SCALEF; v.w = acc[i][3] * SCALEF;
        *(float4*)&out[(size_t)(h * DH + ty * 4 + i) * DIM + n0 + tx * 4] = v;
    }
}

// ---------------- launch ----------------
extern "C" void kernel_launch(void* const* d_in, const int* in_sizes, int n_in,
                              void* d_out, int out_size) {
    const float* x     = (const float*)d_in[0];
    const void*  maskp = d_in[1];
    const float* Wqkv  = (const float*)d_in[2];
    const float* Wout  = (const float*)d_in[3];
    const float* bout  = (const float*)d_in[4];
    float* out = (float*)d_out;

    float *qkv_p = nullptr, *Mb_p = nullptr;
    cudaGetSymbolAddress((void**)&qkv_p, g_qkv);
    cudaGetSymbolAddress((void**)&Mb_p, g_Mb);

    // 1. mask dtype detect + convert
    init_flags_kernel<<<1, 32>>>();
    detect_mask_kernel<<<(MTOT + 255) / 256, 256>>>((const unsigned char*)maskp);
    convert_mask_kernel<<<(MTOT + 255) / 256, 256>>>(maskp);

    // 2. qkv = x @ W_qkv   [16384,1024]x[1024,3072]
    sgemm_kernel<<<dim3(QKVN / 128, MTOT / 128, 1), 256>>>(
        x, Wqkv, qkv_p, nullptr, DIM, DIM, QKVN, QKVN, 0, 0, 0);

    // 3. per-column softmax stats for k
    colstats_partial_kernel<<<dim3(DIM / 256, 8, BB), 256>>>();
    colstats_combine_kernel<<<(BB * DIM) / 256, 256>>>();

    // 4. context partials (T split 4-way, deterministic reduce in mb_kernel)
    context_part_kernel<<<dim3(HEADS, BB, NPART), 256>>>();

    // 5. Mb = SCALE * ctx @ Wout_h  (per batch, per head block)
    mb_kernel<<<dim3(16, BB * HEADS), 256>>>(Wout);

    // 6. final = q @ Mb + b_out   per batch: [4096,1024]x[1024,1024]
    sgemm_kernel<<<dim3(DIM / 128, TT / 128, BB), 256>>>(
        qkv_p /* q = cols 0..1023 */, Mb_p, out, bout,
        DIM, QKVN, DIM, DIM,
        (long long)TT * QKVN, (long long)DIM * DIM, (long long)TT * DIM);
}